// round 1
// baseline (speedup 1.0000x reference)
#include <cuda_runtime.h>

#define B_  4
#define T_  2048
#define C_  1024
#define H_  16
#define HD_ 64

// Scratch (device globals: allocation-free per harness rules)
__device__ float g_qkv[(size_t)B_ * T_ * 3 * C_];   // [B*T, 3C] = [8192, 3072]
__device__ float g_attn[(size_t)B_ * T_ * C_];      // [B*T, C]  = [8192, 1024]

// ---------------------------------------------------------------------------
// SGEMM: C = A[MxK] @ B[KxN] + bias[N].  BM=BN=128, BK=16, 256 thr, 8x8 micro.
// ---------------------------------------------------------------------------
__global__ __launch_bounds__(256)
void sgemm_bias(const float* __restrict__ A, const float* __restrict__ Bm,
                const float* __restrict__ bias, float* __restrict__ Cm,
                int M, int N, int K)
{
    __shared__ float As[16][128];   // [k][m] (A transposed into smem)
    __shared__ float Bs[16][128];   // [k][n]

    const int bx = blockIdx.x;      // N tile
    const int by = blockIdx.y;      // M tile
    const int tid = threadIdx.x;
    const int ty = tid >> 4;        // 0..15
    const int tx = tid & 15;        // 0..15

    float acc[8][8];
#pragma unroll
    for (int i = 0; i < 8; i++)
#pragma unroll
        for (int j = 0; j < 8; j++) acc[i][j] = 0.f;

    const float* Abase = A + (size_t)by * 128 * K;
    const float* Bbase = Bm + (size_t)bx * 128;

    for (int kt = 0; kt < K; kt += 16) {
#pragma unroll
        for (int it = 0; it < 2; it++) {
            int i = tid + it * 256;               // 0..511 float4 slots
            int r  = i >> 2;                      // A tile row (0..127)
            int kq = (i & 3) << 2;                // A k-offset (0,4,8,12)
            float4 a4 = *(const float4*)(Abase + (size_t)r * K + kt + kq);
            As[kq + 0][r] = a4.x;
            As[kq + 1][r] = a4.y;
            As[kq + 2][r] = a4.z;
            As[kq + 3][r] = a4.w;
            int rb = i >> 5;                      // B tile row (0..15)
            int c4 = (i & 31) << 2;               // B col offset
            *(float4*)&Bs[rb][c4] =
                *(const float4*)(Bbase + (size_t)(kt + rb) * N + c4);
        }
        __syncthreads();

#pragma unroll
        for (int kk = 0; kk < 16; kk++) {
            float ar[8], br[8];
            *(float4*)&ar[0] = *(const float4*)&As[kk][ty * 8];
            *(float4*)&ar[4] = *(const float4*)&As[kk][ty * 8 + 4];
            *(float4*)&br[0] = *(const float4*)&Bs[kk][tx * 8];
            *(float4*)&br[4] = *(const float4*)&Bs[kk][tx * 8 + 4];
#pragma unroll
            for (int i = 0; i < 8; i++)
#pragma unroll
                for (int j = 0; j < 8; j++)
                    acc[i][j] += ar[i] * br[j];
        }
        __syncthreads();
    }

#pragma unroll
    for (int i = 0; i < 8; i++) {
        int row = by * 128 + ty * 8 + i;
#pragma unroll
        for (int j4 = 0; j4 < 2; j4++) {
            int col = bx * 128 + tx * 8 + j4 * 4;
            float4 r;
            r.x = acc[i][j4 * 4 + 0] + bias[col + 0];
            r.y = acc[i][j4 * 4 + 1] + bias[col + 1];
            r.z = acc[i][j4 * 4 + 2] + bias[col + 2];
            r.w = acc[i][j4 * 4 + 3] + bias[col + 3];
            *(float4*)(Cm + (size_t)row * N + col) = r;
        }
    }
}

// ---------------------------------------------------------------------------
// RoPE applied in-place to the Q and K regions of g_qkv.
// One thread per (row, rotation-pair): handles dims j and j+32 of one head.
// ---------------------------------------------------------------------------
__global__ __launch_bounds__(256)
void rope_kernel()
{
    int idx = blockIdx.x * 256 + threadIdx.x;     // 0 .. B*T*1024-1
    int p   = idx & 1023;                         // pair index within row
    int row = idx >> 10;                          // b*T + t
    int t   = row & (T_ - 1);
    int slot = p >> 5;                            // 0..31 (16 q-heads, 16 k-heads)
    int j    = p & 31;                            // rotation pair index
    int c    = slot * 64 + j;                     // column in [0, 2048)

    // inv_freq = 10000^(-2j/64) = exp(-j * ln(10000)/32)
    float invf = expf(-0.28782313662425574f * (float)j);
    float angle = (float)t * invf;
    float sv, cv;
    sincosf(angle, &sv, &cv);

    float* rowp = g_qkv + (size_t)row * 3072 + c;
    float x1 = rowp[0];
    float x2 = rowp[32];
    rowp[0]  = x1 * cv - x2 * sv;
    rowp[32] = x2 * cv + x1 * sv;
}

// ---------------------------------------------------------------------------
// Flash attention, causal.  Block = 128 query rows (one thread per query),
// key tiles of 32 staged in smem; online softmax; fp32 throughout.
// ---------------------------------------------------------------------------
__global__ __launch_bounds__(128)
void attn_kernel()
{
    __shared__ float Ks[32][64];
    __shared__ float Vs[32][64];

    const int b  = blockIdx.z;
    const int h  = blockIdx.y;
    const int q0 = blockIdx.x * 128;
    const int tid = threadIdx.x;
    const int row = q0 + tid;

    // Load this thread's (RoPE'd) query row into registers.
    const float* qrow = g_qkv + (size_t)(b * T_ + row) * 3072 + h * 64;
    float q[64];
#pragma unroll
    for (int d = 0; d < 64; d += 4) {
        float4 v = *(const float4*)(qrow + d);
        q[d] = v.x; q[d + 1] = v.y; q[d + 2] = v.z; q[d + 3] = v.w;
    }

    float o[64];
#pragma unroll
    for (int d = 0; d < 64; d++) o[d] = 0.f;
    float mmax = -1e30f;
    float l = 0.f;
    const float scale = 0.125f;   // 1/sqrt(64)

    const int ktiles = (q0 + 128) / 32;
    for (int kt = 0; kt < ktiles; kt++) {
        int k0 = kt * 32;
        // Cooperative K/V tile load: 32 keys x 64 dims each.
#pragma unroll
        for (int i = 0; i < 4; i++) {
            int fi = tid + i * 128;               // float4 slot 0..511
            int r = fi >> 4;                      // key row within tile
            int c = (fi & 15) << 2;               // dim offset
            const float* src = g_qkv + (size_t)(b * T_ + k0 + r) * 3072
                               + 1024 + h * 64 + c;
            *(float4*)&Ks[r][c] = *(const float4*)src;           // K region
            *(float4*)&Vs[r][c] = *(const float4*)(src + 1024);  // V region
        }
        __syncthreads();

        int jlim = row - k0 + 1;                  // #valid keys (may be <=0)
        if (jlim > 32) jlim = 32;

        float s[32];
        float tmax = -1e30f;
#pragma unroll
        for (int j = 0; j < 32; j++) {
            float acc = 0.f;
#pragma unroll
            for (int d4 = 0; d4 < 16; d4++) {
                float4 kv = *(const float4*)&Ks[j][d4 * 4];
                acc += q[d4 * 4 + 0] * kv.x;
                acc += q[d4 * 4 + 1] * kv.y;
                acc += q[d4 * 4 + 2] * kv.z;
                acc += q[d4 * 4 + 3] * kv.w;
            }
            s[j] = (j < jlim) ? acc * scale : -1e30f;
            tmax = fmaxf(tmax, s[j]);
        }

        if (tmax > mmax) {
            float f = __expf(mmax - tmax);
            l *= f;
#pragma unroll
            for (int d = 0; d < 64; d++) o[d] *= f;
            mmax = tmax;
        }

#pragma unroll
        for (int j = 0; j < 32; j++) {
            float p = __expf(s[j] - mmax);        // masked keys underflow to 0
            l += p;
#pragma unroll
            for (int d4 = 0; d4 < 16; d4++) {
                float4 vv = *(const float4*)&Vs[j][d4 * 4];
                o[d4 * 4 + 0] += p * vv.x;
                o[d4 * 4 + 1] += p * vv.y;
                o[d4 * 4 + 2] += p * vv.z;
                o[d4 * 4 + 3] += p * vv.w;
            }
        }
        __syncthreads();
    }

    float inv = 1.f / l;
    float* orow = g_attn + (size_t)(b * T_ + row) * 1024 + h * 64;
#pragma unroll
    for (int d = 0; d < 64; d += 4) {
        float4 r;
        r.x = o[d] * inv; r.y = o[d + 1] * inv;
        r.z = o[d + 2] * inv; r.w = o[d + 3] * inv;
        *(float4*)(orow + d) = r;
    }
}

// ---------------------------------------------------------------------------
extern "C" void kernel_launch(void* const* d_in, const int* in_sizes, int n_in,
                              void* d_out, int out_size)
{
    const float* x    = (const float*)d_in[0];
    const float* Wqkv = (const float*)d_in[1];
    const float* bqkv = (const float*)d_in[2];
    const float* Wout = (const float*)d_in[3];
    const float* bout = (const float*)d_in[4];
    float* out = (float*)d_out;

    static float* qkv_p  = nullptr;
    static float* attn_p = nullptr;
    if (!qkv_p) {
        cudaGetSymbolAddress((void**)&qkv_p, g_qkv);
        cudaGetSymbolAddress((void**)&attn_p, g_attn);
    }

    const int M = B_ * T_;   // 8192

    // 1) QKV projection: [8192,1024] @ [1024,3072] + bias
    dim3 g1(3 * C_ / 128, M / 128);
    sgemm_bias<<<g1, 256>>>(x, Wqkv, bqkv, qkv_p, M, 3 * C_, C_);

    // 2) RoPE on Q and K, in place
    rope_kernel<<<(M * 1024) / 256, 256>>>();

    // 3) Causal flash attention
    dim3 ga(T_ / 128, H_, B_);
    attn_kernel<<<ga, 128>>>();

    // 4) Output projection: [8192,1024] @ [1024,1024] + bias
    dim3 g2(C_ / 128, M / 128);
    sgemm_bias<<<g2, 256>>>(attn_p, Wout, bout, out, M, C_, C_);
}

// round 2
// speedup vs baseline: 1.2181x; 1.2181x over previous
#include <cuda_runtime.h>

#define B_  4
#define T_  2048
#define C_  1024
#define H_  16

// Scratch (device globals: allocation-free per harness rules)
__device__ float g_qkv[(size_t)B_ * T_ * 3 * C_];   // [B*T, 3C]
__device__ float g_attn[(size_t)B_ * T_ * C_];      // [B*T, C]

// ---------------------------------------------------------------------------
// SGEMM: C = A[MxK] @ B[KxN] + bias[N].  BM=BN=128, BK=16, 256 thr, 8x8 micro,
// double-buffered smem with register-staged global prefetch.
// ---------------------------------------------------------------------------
__global__ __launch_bounds__(256)
void sgemm_bias(const float* __restrict__ A, const float* __restrict__ Bm,
                const float* __restrict__ bias, float* __restrict__ Cm,
                int M, int N, int K)
{
    __shared__ float As[2][16][128];   // [k][m]
    __shared__ float Bs[2][16][128];   // [k][n]

    const int bx = blockIdx.x;
    const int by = blockIdx.y;
    const int tid = threadIdx.x;
    const int ty = tid >> 4;
    const int tx = tid & 15;

    float acc[8][8];
#pragma unroll
    for (int i = 0; i < 8; i++)
#pragma unroll
        for (int j = 0; j < 8; j++) acc[i][j] = 0.f;

    const float* Abase = A + (size_t)by * 128 * K;
    const float* Bbase = Bm + (size_t)bx * 128;

    // load-slot indices (2 float4 slots per thread for A and for B)
    const int a_r0 = tid >> 2;            // 0..63  (slot1: +64)
    const int a_k  = (tid & 3) << 2;      // 0,4,8,12
    const int b_r0 = tid >> 5;            // 0..7   (slot1: +8)
    const int b_c  = (tid & 31) << 2;     // 0..124

    float4 ra[2], rb[2];

#define LOADG(kt)                                                              \
    do {                                                                       \
        ra[0] = *(const float4*)(Abase + (size_t)a_r0 * K + (kt) + a_k);       \
        ra[1] = *(const float4*)(Abase + (size_t)(a_r0 + 64) * K + (kt) + a_k);\
        rb[0] = *(const float4*)(Bbase + (size_t)((kt) + b_r0) * N + b_c);     \
        rb[1] = *(const float4*)(Bbase + (size_t)((kt) + b_r0 + 8) * N + b_c); \
    } while (0)

#define STORES(bf)                                                             \
    do {                                                                       \
        As[bf][a_k + 0][a_r0] = ra[0].x;  As[bf][a_k + 1][a_r0] = ra[0].y;     \
        As[bf][a_k + 2][a_r0] = ra[0].z;  As[bf][a_k + 3][a_r0] = ra[0].w;     \
        As[bf][a_k + 0][a_r0 + 64] = ra[1].x;                                  \
        As[bf][a_k + 1][a_r0 + 64] = ra[1].y;                                  \
        As[bf][a_k + 2][a_r0 + 64] = ra[1].z;                                  \
        As[bf][a_k + 3][a_r0 + 64] = ra[1].w;                                  \
        *(float4*)&Bs[bf][b_r0][b_c]     = rb[0];                              \
        *(float4*)&Bs[bf][b_r0 + 8][b_c] = rb[1];                              \
    } while (0)

    LOADG(0);
    STORES(0);
    __syncthreads();

    int buf = 0;
    for (int kt = 16;; kt += 16) {
        const bool more = (kt < K);
        if (more) LOADG(kt);

#pragma unroll
        for (int kk = 0; kk < 16; kk++) {
            float ar[8], br[8];
            *(float4*)&ar[0] = *(const float4*)&As[buf][kk][ty * 8];
            *(float4*)&ar[4] = *(const float4*)&As[buf][kk][ty * 8 + 4];
            *(float4*)&br[0] = *(const float4*)&Bs[buf][kk][tx * 8];
            *(float4*)&br[4] = *(const float4*)&Bs[buf][kk][tx * 8 + 4];
#pragma unroll
            for (int i = 0; i < 8; i++)
#pragma unroll
                for (int j = 0; j < 8; j++)
                    acc[i][j] += ar[i] * br[j];
        }

        if (!more) break;
        STORES(buf ^ 1);
        __syncthreads();
        buf ^= 1;
    }

#pragma unroll
    for (int i = 0; i < 8; i++) {
        int row = by * 128 + ty * 8 + i;
#pragma unroll
        for (int j4 = 0; j4 < 2; j4++) {
            int col = bx * 128 + tx * 8 + j4 * 4;
            float4 r;
            r.x = acc[i][j4 * 4 + 0] + bias[col + 0];
            r.y = acc[i][j4 * 4 + 1] + bias[col + 1];
            r.z = acc[i][j4 * 4 + 2] + bias[col + 2];
            r.w = acc[i][j4 * 4 + 3] + bias[col + 3];
            *(float4*)(Cm + (size_t)row * N + col) = r;
        }
    }
#undef LOADG
#undef STORES
}

// ---------------------------------------------------------------------------
// RoPE applied in-place to Q and K regions of g_qkv.
// ---------------------------------------------------------------------------
__global__ __launch_bounds__(256)
void rope_kernel()
{
    int idx = blockIdx.x * 256 + threadIdx.x;
    int p   = idx & 1023;
    int row = idx >> 10;
    int t   = row & (T_ - 1);
    int slot = p >> 5;
    int j    = p & 31;
    int c    = slot * 64 + j;

    float invf = expf(-0.28782313662425574f * (float)j);
    float angle = (float)t * invf;
    float sv, cv;
    sincosf(angle, &sv, &cv);

    float* rowp = g_qkv + (size_t)row * 3072 + c;
    float x1 = rowp[0];
    float x2 = rowp[32];
    rowp[0]  = x1 * cv - x2 * sv;
    rowp[32] = x2 * cv + x1 * sv;
}

// ---------------------------------------------------------------------------
// Flash attention (causal), GEMM-structured.
// Block: 64 queries x one head. 256 threads, 4x4 micro-tiles.
// smem: Qt[d][q] (pad 68), Kt[d][k] (pad 68), Pt[q][k] (pad 68), Vs[k][d].
// ---------------------------------------------------------------------------
#define PADA 68

__global__ __launch_bounds__(256)
void attn_kernel()
{
    extern __shared__ float smf[];
    float* Qt = smf;                  // 64*68
    float* Kt = Qt + 64 * PADA;       // 64*68
    float* Pt = Kt + 64 * PADA;       // 64*68
    float* Vs = Pt + 64 * PADA;       // 64*64

    const int b  = blockIdx.z;
    const int h  = blockIdx.y;
    const int q0 = blockIdx.x * 64;
    const int tid = threadIdx.x;
    const int ty = tid >> 4;          // 0..15 -> 4 query rows
    const int tx = tid & 15;          // 0..15 -> 4 key cols / 4 dv cols

    // --- load Q transposed: lanes span rows (conflict-free STS) ---
    {
        const int r  = tid & 63;
        const int hi = tid >> 6;      // 0..3
        const float* qb = g_qkv + (size_t)(b * T_ + q0 + r) * 3072 + h * 64;
#pragma unroll
        for (int s2 = 0; s2 < 4; s2++) {
            int d0 = hi * 16 + s2 * 4;
            float4 v = *(const float4*)(qb + d0);
            Qt[(d0 + 0) * PADA + r] = v.x;
            Qt[(d0 + 1) * PADA + r] = v.y;
            Qt[(d0 + 2) * PADA + r] = v.z;
            Qt[(d0 + 3) * PADA + r] = v.w;
        }
    }

    float o[4][4];
#pragma unroll
    for (int i = 0; i < 4; i++)
#pragma unroll
        for (int j = 0; j < 4; j++) o[i][j] = 0.f;
    float m[4], l[4];
#pragma unroll
    for (int i = 0; i < 4; i++) { m[i] = -1e30f; l[i] = 0.f; }

    const int ntiles = blockIdx.x + 1;
    for (int kt = 0; kt < ntiles; kt++) {
        const int k0 = kt * 64;

        __syncthreads();   // protect Kt/Vs (and Qt on first iter) from prior reads

        // --- load K transposed (lanes span rows), V natural (coalesced) ---
        {
            const int r  = tid & 63;
            const int hi = tid >> 6;
            const float* kb = g_qkv + (size_t)(b * T_ + k0 + r) * 3072 + 1024 + h * 64;
#pragma unroll
            for (int s2 = 0; s2 < 4; s2++) {
                int d0 = hi * 16 + s2 * 4;
                float4 v = *(const float4*)(kb + d0);
                Kt[(d0 + 0) * PADA + r] = v.x;
                Kt[(d0 + 1) * PADA + r] = v.y;
                Kt[(d0 + 2) * PADA + r] = v.z;
                Kt[(d0 + 3) * PADA + r] = v.w;
            }
#pragma unroll
            for (int it = 0; it < 4; it++) {
                int fi = tid + it * 256;
                int rr = fi >> 4;
                int dd = (fi & 15) << 2;
                *(float4*)(Vs + rr * 64 + dd) =
                    *(const float4*)(g_qkv + (size_t)(b * T_ + k0 + rr) * 3072
                                     + 2048 + h * 64 + dd);
            }
        }
        __syncthreads();

        // --- S = Q K^T (4x4 micro-tile per thread) ---
        float s[4][4];
#pragma unroll
        for (int i = 0; i < 4; i++)
#pragma unroll
            for (int j = 0; j < 4; j++) s[i][j] = 0.f;

#pragma unroll 16
        for (int d = 0; d < 64; d++) {
            float4 aq = *(const float4*)(Qt + d * PADA + ty * 4);
            float4 bk = *(const float4*)(Kt + d * PADA + tx * 4);
            float a0 = aq.x, a1 = aq.y, a2 = aq.z, a3 = aq.w;
            s[0][0] += a0 * bk.x; s[0][1] += a0 * bk.y; s[0][2] += a0 * bk.z; s[0][3] += a0 * bk.w;
            s[1][0] += a1 * bk.x; s[1][1] += a1 * bk.y; s[1][2] += a1 * bk.z; s[1][3] += a1 * bk.w;
            s[2][0] += a2 * bk.x; s[2][1] += a2 * bk.y; s[2][2] += a2 * bk.z; s[2][3] += a2 * bk.w;
            s[3][0] += a3 * bk.x; s[3][1] += a3 * bk.y; s[3][2] += a3 * bk.z; s[3][3] += a3 * bk.w;
        }

        // --- scale + causal mask (only diagonal tile) ---
        const bool diag = (kt == ntiles - 1);
#pragma unroll
        for (int i = 0; i < 4; i++)
#pragma unroll
            for (int j = 0; j < 4; j++) {
                float v = s[i][j] * 0.125f;
                if (diag && (k0 + tx * 4 + j > q0 + ty * 4 + i)) v = -1e30f;
                s[i][j] = v;
            }

        // --- online softmax per query row, write P to smem ---
#pragma unroll
        for (int i = 0; i < 4; i++) {
            float tm = fmaxf(fmaxf(s[i][0], s[i][1]), fmaxf(s[i][2], s[i][3]));
            tm = fmaxf(tm, __shfl_xor_sync(0xffffffffu, tm, 1));
            tm = fmaxf(tm, __shfl_xor_sync(0xffffffffu, tm, 2));
            tm = fmaxf(tm, __shfl_xor_sync(0xffffffffu, tm, 4));
            tm = fmaxf(tm, __shfl_xor_sync(0xffffffffu, tm, 8));
            float mn = fmaxf(m[i], tm);
            float f  = __expf(m[i] - mn);
            m[i] = mn;
            float rs = 0.f;
#pragma unroll
            for (int j = 0; j < 4; j++) { s[i][j] = __expf(s[i][j] - mn); rs += s[i][j]; }
            rs += __shfl_xor_sync(0xffffffffu, rs, 1);
            rs += __shfl_xor_sync(0xffffffffu, rs, 2);
            rs += __shfl_xor_sync(0xffffffffu, rs, 4);
            rs += __shfl_xor_sync(0xffffffffu, rs, 8);
            l[i] = l[i] * f + rs;
#pragma unroll
            for (int j = 0; j < 4; j++) o[i][j] *= f;
            float4 pv = make_float4(s[i][0], s[i][1], s[i][2], s[i][3]);
            *(float4*)(Pt + (ty * 4 + i) * PADA + tx * 4) = pv;
        }
        __syncthreads();

        // --- O += P V (4x4 micro-tile per thread) ---
#pragma unroll 16
        for (int kk = 0; kk < 64; kk++) {
            float4 bv = *(const float4*)(Vs + kk * 64 + tx * 4);
            float a0 = Pt[(ty * 4 + 0) * PADA + kk];
            float a1 = Pt[(ty * 4 + 1) * PADA + kk];
            float a2 = Pt[(ty * 4 + 2) * PADA + kk];
            float a3 = Pt[(ty * 4 + 3) * PADA + kk];
            o[0][0] += a0 * bv.x; o[0][1] += a0 * bv.y; o[0][2] += a0 * bv.z; o[0][3] += a0 * bv.w;
            o[1][0] += a1 * bv.x; o[1][1] += a1 * bv.y; o[1][2] += a1 * bv.z; o[1][3] += a1 * bv.w;
            o[2][0] += a2 * bv.x; o[2][1] += a2 * bv.y; o[2][2] += a2 * bv.z; o[2][3] += a2 * bv.w;
            o[3][0] += a3 * bv.x; o[3][1] += a3 * bv.y; o[3][2] += a3 * bv.z; o[3][3] += a3 * bv.w;
        }
    }

    // --- epilogue ---
#pragma unroll
    for (int i = 0; i < 4; i++) {
        float inv = 1.f / l[i];
        float4 r = make_float4(o[i][0] * inv, o[i][1] * inv,
                               o[i][2] * inv, o[i][3] * inv);
        *(float4*)(g_attn + (size_t)(b * T_ + q0 + ty * 4 + i) * 1024
                   + h * 64 + tx * 4) = r;
    }
}

static const int ATTN_SMEM = (3 * 64 * PADA + 64 * 64) * 4;   // 68608 B

// ---------------------------------------------------------------------------
extern "C" void kernel_launch(void* const* d_in, const int* in_sizes, int n_in,
                              void* d_out, int out_size)
{
    const float* x    = (const float*)d_in[0];
    const float* Wqkv = (const float*)d_in[1];
    const float* bqkv = (const float*)d_in[2];
    const float* Wout = (const float*)d_in[3];
    const float* bout = (const float*)d_in[4];
    float* out = (float*)d_out;

    float* qkv_p  = nullptr;
    float* attn_p = nullptr;
    cudaGetSymbolAddress((void**)&qkv_p, g_qkv);
    cudaGetSymbolAddress((void**)&attn_p, g_attn);
    cudaFuncSetAttribute(attn_kernel,
                         cudaFuncAttributeMaxDynamicSharedMemorySize, ATTN_SMEM);

    const int M = B_ * T_;   // 8192

    // 1) QKV projection
    dim3 g1(3 * C_ / 128, M / 128);
    sgemm_bias<<<g1, 256>>>(x, Wqkv, bqkv, qkv_p, M, 3 * C_, C_);

    // 2) RoPE (in place on Q,K)
    rope_kernel<<<(M * 1024) / 256, 256>>>();

    // 3) Causal flash attention
    dim3 ga(T_ / 64, H_, B_);
    attn_kernel<<<ga, 256, ATTN_SMEM>>>();

    // 4) Output projection
    dim3 g2(C_ / 128, M / 128);
    sgemm_bias<<<g2, 256>>>(attn_p, Wout, bout, out, M, C_, C_);
}

// round 9
// speedup vs baseline: 1.9278x; 1.5825x over previous
#include <cuda_runtime.h>
#include <cuda_bf16.h>
#include <cstdint>

#define B_  4
#define T_  2048
#define C_  1024
#define H_  16

// ---------------- device scratch (no allocs allowed) ----------------
__device__ float g_qkv[(size_t)B_ * T_ * 3 * C_];            // [8192, 3072] fp32
__device__ __nv_bfloat16 g_ah[(size_t)B_ * T_ * C_];         // A hi split [8192,1024]
__device__ __nv_bfloat16 g_al[(size_t)B_ * T_ * C_];         // A lo split
__device__ __nv_bfloat16 g_wqh[(size_t)3 * C_ * C_];         // W_qkv^T hi [3072,1024]
__device__ __nv_bfloat16 g_wql[(size_t)3 * C_ * C_];
__device__ __nv_bfloat16 g_woh[(size_t)C_ * C_];             // W_out^T hi [1024,1024]
__device__ __nv_bfloat16 g_wol[(size_t)C_ * C_];

__device__ __forceinline__ uint32_t smem_u32(const void* p) {
    uint32_t a;
    asm("{ .reg .u64 t; cvta.to.shared.u64 t, %1; cvt.u32.u64 %0, t; }" : "=r"(a) : "l"(p));
    return a;
}

#define CP16(dst, src) \
    asm volatile("cp.async.cg.shared.global [%0], [%1], 16;" :: "r"(dst), "l"(src))
#define CP_COMMIT() asm volatile("cp.async.commit_group;")
#define CP_WAIT1()  asm volatile("cp.async.wait_group 1;")
#define CP_WAIT0()  asm volatile("cp.async.wait_group 0;")

#define LDSM_X4(r0, r1, r2, r3, a) \
    asm volatile("ldmatrix.sync.aligned.m8n8.x4.shared.b16 {%0,%1,%2,%3}, [%4];" \
        : "=r"(r0), "=r"(r1), "=r"(r2), "=r"(r3) : "r"(a))

#define MMA_BF16(d, a, bv0, bv1) \
    asm volatile("mma.sync.aligned.m16n8k16.row.col.f32.bf16.bf16.f32 " \
        "{%0,%1,%2,%3}, {%4,%5,%6,%7}, {%8,%9}, {%0,%1,%2,%3};" \
        : "+f"((d)[0]), "+f"((d)[1]), "+f"((d)[2]), "+f"((d)[3]) \
        : "r"((a)[0]), "r"((a)[1]), "r"((a)[2]), "r"((a)[3]), "r"(bv0), "r"(bv1))

// ---------------- split / transpose prep ----------------
__global__ __launch_bounds__(256)
void split_kernel(const float* __restrict__ src, __nv_bfloat16* __restrict__ Dh,
                  __nv_bfloat16* __restrict__ Dl, int n4)
{
    int i = blockIdx.x * 256 + threadIdx.x;
    if (i >= n4) return;
    float4 v = *(const float4*)(src + (size_t)i * 4);
    float vs[4] = {v.x, v.y, v.z, v.w};
    uint32_t h01 = 0, h23 = 0, l01 = 0, l23 = 0;
#pragma unroll
    for (int k = 0; k < 4; k++) {
        __nv_bfloat16 hb = __float2bfloat16(vs[k]);
        __nv_bfloat16 lb = __float2bfloat16(vs[k] - __bfloat162float(hb));
        uint32_t hu = (uint32_t)__bfloat16_as_ushort(hb);
        uint32_t lu = (uint32_t)__bfloat16_as_ushort(lb);
        if (k < 2) { h01 |= hu << (16 * k); l01 |= lu << (16 * k); }
        else       { h23 |= hu << (16 * (k - 2)); l23 |= lu << (16 * (k - 2)); }
    }
    *(uint2*)(Dh + (size_t)i * 4) = make_uint2(h01, h23);
    *(uint2*)(Dl + (size_t)i * 4) = make_uint2(l01, l23);
}

__global__ __launch_bounds__(256)
void transpose_split(const float* __restrict__ W, __nv_bfloat16* __restrict__ Th,
                     __nv_bfloat16* __restrict__ Tl, int K, int N)
{   // W [K,N] row-major -> Th/Tl [N,K] row-major (bf16 hi/lo)
    __shared__ float t[32][33];
    int tx = threadIdx.x, ty = threadIdx.y;       // block (32, 8)
    int n = blockIdx.x * 32 + tx;
    int k = blockIdx.y * 32 + ty;
#pragma unroll
    for (int j = 0; j < 32; j += 8)
        t[ty + j][tx] = W[(size_t)(k + j) * N + n];
    __syncthreads();
    int k2 = blockIdx.y * 32 + tx;
    int n2 = blockIdx.x * 32 + ty;
#pragma unroll
    for (int j = 0; j < 32; j += 8) {
        float v = t[tx][ty + j];
        __nv_bfloat16 hb = __float2bfloat16(v);
        __nv_bfloat16 lb = __float2bfloat16(v - __bfloat162float(hb));
        Th[(size_t)(n2 + j) * K + k2] = hb;
        Tl[(size_t)(n2 + j) * K + k2] = lb;
    }
}

// ---------------- HMMA (mma.sync) GEMM: C = A @ B^T + bias ----------------
// A split (Ah/Al) [M,K] bf16 row-major; B split (Bh/Bl) [N,K] bf16 row-major.
// CTA 128x128, 8 warps (4x2), warp tile 32x64; BK=32; 2-stage cp.async pipe.
// 3 passes: AhBh + AhBl + AlBh.
#define BKc   32
#define LDAB  40                       // bf16 per smem row (pad: 80B stride)
#define ROWB  (LDAB * 2)               // 80 bytes
#define STG_BYTES (128 * ROWB)         // 10240 per array per stage
#define ARR_BYTES (2 * STG_BYTES)
#define SM_AH 0
#define SM_AL (1 * ARR_BYTES)
#define SM_BH (2 * ARR_BYTES)
#define SM_BL (3 * ARR_BYTES)
#define GEMM_SMEM (4 * ARR_BYTES)      // 81920

__global__ __launch_bounds__(256)
void gemm_mma(const __nv_bfloat16* __restrict__ Ah, const __nv_bfloat16* __restrict__ Al,
              const __nv_bfloat16* __restrict__ Bh, const __nv_bfloat16* __restrict__ Bl,
              const float* __restrict__ bias, float* __restrict__ Cm,
              int M, int N, int K)
{
    extern __shared__ char sm[];
    const uint32_t sbase = smem_u32(sm);
    const int tid = threadIdx.x;
    const int wid = tid >> 5;
    const int lane = tid & 31;
    const int m0 = blockIdx.y * 128;
    const int n0 = blockIdx.x * 128;
    const int wm = (wid >> 1) * 32;    // warp m offset in tile
    const int wn = (wid & 1) * 64;     // warp n offset in tile

    float acc[2][8][4];
#pragma unroll
    for (int i = 0; i < 2; i++)
#pragma unroll
        for (int j = 0; j < 8; j++)
#pragma unroll
            for (int q = 0; q < 4; q++) acc[i][j][q] = 0.f;

    const int r_ld = tid >> 2;         // 0..63
    const int g_ld = tid & 3;          // 16B chunk within row

#define LOAD_STAGE(stg, kt)                                                     \
    do {                                                                        \
        uint32_t so = (uint32_t)(stg) * STG_BYTES;                              \
        _Pragma("unroll")                                                       \
        for (int it = 0; it < 2; it++) {                                        \
            int r = r_ld + it * 64;                                             \
            uint32_t d = so + (uint32_t)r * ROWB + g_ld * 16;                   \
            size_t ga = (size_t)(m0 + r) * K + (kt) + g_ld * 8;                 \
            size_t gb = (size_t)(n0 + r) * K + (kt) + g_ld * 8;                 \
            CP16(sbase + SM_AH + d, Ah + ga);                                   \
            CP16(sbase + SM_AL + d, Al + ga);                                   \
            CP16(sbase + SM_BH + d, Bh + gb);                                   \
            CP16(sbase + SM_BL + d, Bl + gb);                                   \
        }                                                                       \
    } while (0)

    // ldmatrix lane addressing
    const uint32_t a_row = wm + (lane & 15);
    const uint32_t a_col = (lane >> 4) * 8;
    const uint32_t b_row = wn + ((lane >> 4) << 3) + (lane & 7);
    const uint32_t b_col = ((lane >> 3) & 1) * 8;

    const int nchunks = K / BKc;       // 32

    LOAD_STAGE(0, 0);
    CP_COMMIT();

    for (int c = 0; c < nchunks; c++) {
        if (c + 1 < nchunks) {
            LOAD_STAGE((c + 1) & 1, (c + 1) * BKc);
            CP_COMMIT();
            CP_WAIT1();
        } else {
            CP_WAIT0();
        }
        __syncthreads();

        const uint32_t so = (uint32_t)(c & 1) * STG_BYTES;
#pragma unroll
        for (int ks = 0; ks < 2; ks++) {          // k16 steps within chunk
            const uint32_t kc = (ks * 16 + a_col) * 2;
            const uint32_t kb = (ks * 16 + b_col) * 2;
            uint32_t ah[2][4], al[2][4], bh[4][4], bl[4][4];
#pragma unroll
            for (int mt = 0; mt < 2; mt++) {
                uint32_t ra = so + (a_row + mt * 16) * ROWB + kc;
                LDSM_X4(ah[mt][0], ah[mt][1], ah[mt][2], ah[mt][3], sbase + SM_AH + ra);
                LDSM_X4(al[mt][0], al[mt][1], al[mt][2], al[mt][3], sbase + SM_AL + ra);
            }
#pragma unroll
            for (int ng = 0; ng < 4; ng++) {
                uint32_t rb = so + (b_row + ng * 16) * ROWB + kb;
                LDSM_X4(bh[ng][0], bh[ng][1], bh[ng][2], bh[ng][3], sbase + SM_BH + rb);
                LDSM_X4(bl[ng][0], bl[ng][1], bl[ng][2], bl[ng][3], sbase + SM_BL + rb);
            }
#pragma unroll
            for (int mt = 0; mt < 2; mt++)
#pragma unroll
                for (int nt = 0; nt < 8; nt++) {
                    const int ng = nt >> 1, p = (nt & 1) * 2;
                    MMA_BF16(acc[mt][nt], ah[mt], bh[ng][p], bh[ng][p + 1]);
                    MMA_BF16(acc[mt][nt], ah[mt], bl[ng][p], bl[ng][p + 1]);
                    MMA_BF16(acc[mt][nt], al[mt], bh[ng][p], bh[ng][p + 1]);
                }
        }
        __syncthreads();
    }

    // epilogue: bias + store fp32
    const int er = lane >> 2;          // 0..7
    const int ec = (lane & 3) * 2;
#pragma unroll
    for (int mt = 0; mt < 2; mt++) {
        int row = m0 + wm + mt * 16 + er;
#pragma unroll
        for (int nt = 0; nt < 8; nt++) {
            int col = n0 + wn + nt * 8 + ec;
            float b0 = bias[col], b1 = bias[col + 1];
            float2 v0 = make_float2(acc[mt][nt][0] + b0, acc[mt][nt][1] + b1);
            float2 v1 = make_float2(acc[mt][nt][2] + b0, acc[mt][nt][3] + b1);
            *(float2*)(Cm + (size_t)row * N + col) = v0;
            *(float2*)(Cm + (size_t)(row + 8) * N + col) = v1;
        }
    }
#undef LOAD_STAGE
}

// ---------------- RoPE (in place on Q,K of g_qkv) ----------------
__global__ __launch_bounds__(256)
void rope_kernel()
{
    int idx = blockIdx.x * 256 + threadIdx.x;
    int p   = idx & 1023;
    int row = idx >> 10;
    int t   = row & (T_ - 1);
    int slot = p >> 5;
    int j    = p & 31;
    int c    = slot * 64 + j;

    float invf = expf(-0.28782313662425574f * (float)j);
    float angle = (float)t * invf;
    float sv, cv;
    sincosf(angle, &sv, &cv);

    float* rowp = g_qkv + (size_t)row * 3072 + c;
    float x1 = rowp[0];
    float x2 = rowp[32];
    rowp[0]  = x1 * cv - x2 * sv;
    rowp[32] = x2 * cv + x1 * sv;
}

// ---------------- Flash attention (causal), fp32, GEMM-structured ----------------
#define PADA 68

__global__ __launch_bounds__(256)
void attn_kernel()
{
    extern __shared__ float smf[];
    float* Qt = smf;
    float* Kt = Qt + 64 * PADA;
    float* Pt = Kt + 64 * PADA;
    float* Vs = Pt + 64 * PADA;

    const int b  = blockIdx.z;
    const int h  = blockIdx.y;
    const int q0 = blockIdx.x * 64;
    const int tid = threadIdx.x;
    const int ty = tid >> 4;
    const int tx = tid & 15;

    {
        const int r  = tid & 63;
        const int hi = tid >> 6;
        const float* qb = g_qkv + (size_t)(b * T_ + q0 + r) * 3072 + h * 64;
#pragma unroll
        for (int s2 = 0; s2 < 4; s2++) {
            int d0 = hi * 16 + s2 * 4;
            float4 v = *(const float4*)(qb + d0);
            Qt[(d0 + 0) * PADA + r] = v.x;
            Qt[(d0 + 1) * PADA + r] = v.y;
            Qt[(d0 + 2) * PADA + r] = v.z;
            Qt[(d0 + 3) * PADA + r] = v.w;
        }
    }

    float o[4][4];
#pragma unroll
    for (int i = 0; i < 4; i++)
#pragma unroll
        for (int j = 0; j < 4; j++) o[i][j] = 0.f;
    float m[4], l[4];
#pragma unroll
    for (int i = 0; i < 4; i++) { m[i] = -1e30f; l[i] = 0.f; }

    const int ntiles = blockIdx.x + 1;
    for (int kt = 0; kt < ntiles; kt++) {
        const int k0 = kt * 64;
        __syncthreads();
        {
            const int r  = tid & 63;
            const int hi = tid >> 6;
            const float* kb = g_qkv + (size_t)(b * T_ + k0 + r) * 3072 + 1024 + h * 64;
#pragma unroll
            for (int s2 = 0; s2 < 4; s2++) {
                int d0 = hi * 16 + s2 * 4;
                float4 v = *(const float4*)(kb + d0);
                Kt[(d0 + 0) * PADA + r] = v.x;
                Kt[(d0 + 1) * PADA + r] = v.y;
                Kt[(d0 + 2) * PADA + r] = v.z;
                Kt[(d0 + 3) * PADA + r] = v.w;
            }
#pragma unroll
            for (int it = 0; it < 4; it++) {
                int fi = tid + it * 256;
                int rr = fi >> 4;
                int dd = (fi & 15) << 2;
                *(float4*)(Vs + rr * 64 + dd) =
                    *(const float4*)(g_qkv + (size_t)(b * T_ + k0 + rr) * 3072
                                     + 2048 + h * 64 + dd);
            }
        }
        __syncthreads();

        float s[4][4];
#pragma unroll
        for (int i = 0; i < 4; i++)
#pragma unroll
            for (int j = 0; j < 4; j++) s[i][j] = 0.f;

#pragma unroll 16
        for (int d = 0; d < 64; d++) {
            float4 aq = *(const float4*)(Qt + d * PADA + ty * 4);
            float4 bk = *(const float4*)(Kt + d * PADA + tx * 4);
            float a0 = aq.x, a1 = aq.y, a2 = aq.z, a3 = aq.w;
            s[0][0] += a0 * bk.x; s[0][1] += a0 * bk.y; s[0][2] += a0 * bk.z; s[0][3] += a0 * bk.w;
            s[1][0] += a1 * bk.x; s[1][1] += a1 * bk.y; s[1][2] += a1 * bk.z; s[1][3] += a1 * bk.w;
            s[2][0] += a2 * bk.x; s[2][1] += a2 * bk.y; s[2][2] += a2 * bk.z; s[2][3] += a2 * bk.w;
            s[3][0] += a3 * bk.x; s[3][1] += a3 * bk.y; s[3][2] += a3 * bk.z; s[3][3] += a3 * bk.w;
        }

        const bool diag = (kt == ntiles - 1);
#pragma unroll
        for (int i = 0; i < 4; i++)
#pragma unroll
            for (int j = 0; j < 4; j++) {
                float v = s[i][j] * 0.125f;
                if (diag && (k0 + tx * 4 + j > q0 + ty * 4 + i)) v = -1e30f;
                s[i][j] = v;
            }

#pragma unroll
        for (int i = 0; i < 4; i++) {
            float tm = fmaxf(fmaxf(s[i][0], s[i][1]), fmaxf(s[i][2], s[i][3]));
            tm = fmaxf(tm, __shfl_xor_sync(0xffffffffu, tm, 1));
            tm = fmaxf(tm, __shfl_xor_sync(0xffffffffu, tm, 2));
            tm = fmaxf(tm, __shfl_xor_sync(0xffffffffu, tm, 4));
            tm = fmaxf(tm, __shfl_xor_sync(0xffffffffu, tm, 8));
            float mn = fmaxf(m[i], tm);
            float f  = __expf(m[i] - mn);
            m[i] = mn;
            float rs = 0.f;
#pragma unroll
            for (int j = 0; j < 4; j++) { s[i][j] = __expf(s[i][j] - mn); rs += s[i][j]; }
            rs += __shfl_xor_sync(0xffffffffu, rs, 1);
            rs += __shfl_xor_sync(0xffffffffu, rs, 2);
            rs += __shfl_xor_sync(0xffffffffu, rs, 4);
            rs += __shfl_xor_sync(0xffffffffu, rs, 8);
            l[i] = l[i] * f + rs;
#pragma unroll
            for (int j = 0; j < 4; j++) o[i][j] *= f;
            float4 pv = make_float4(s[i][0], s[i][1], s[i][2], s[i][3]);
            *(float4*)(Pt + (ty * 4 + i) * PADA + tx * 4) = pv;
        }
        __syncthreads();

#pragma unroll 16
        for (int kk = 0; kk < 64; kk++) {
            float4 bv = *(const float4*)(Vs + kk * 64 + tx * 4);
            float a0 = Pt[(ty * 4 + 0) * PADA + kk];
            float a1 = Pt[(ty * 4 + 1) * PADA + kk];
            float a2 = Pt[(ty * 4 + 2) * PADA + kk];
            float a3 = Pt[(ty * 4 + 3) * PADA + kk];
            o[0][0] += a0 * bv.x; o[0][1] += a0 * bv.y; o[0][2] += a0 * bv.z; o[0][3] += a0 * bv.w;
            o[1][0] += a1 * bv.x; o[1][1] += a1 * bv.y; o[1][2] += a1 * bv.z; o[1][3] += a1 * bv.w;
            o[2][0] += a2 * bv.x; o[2][1] += a2 * bv.y; o[2][2] += a2 * bv.z; o[2][3] += a2 * bv.w;
            o[3][0] += a3 * bv.x; o[3][1] += a3 * bv.y; o[3][2] += a3 * bv.z; o[3][3] += a3 * bv.w;
        }
    }

    // epilogue: normalize + bf16 hi/lo split directly into g_ah/g_al
#pragma unroll
    for (int i = 0; i < 4; i++) {
        float inv = 1.f / l[i];
        float vs[4] = {o[i][0] * inv, o[i][1] * inv, o[i][2] * inv, o[i][3] * inv};
        uint32_t h01 = 0, h23 = 0, l01 = 0, l23 = 0;
#pragma unroll
        for (int k = 0; k < 4; k++) {
            __nv_bfloat16 hb = __float2bfloat16(vs[k]);
            __nv_bfloat16 lb = __float2bfloat16(vs[k] - __bfloat162float(hb));
            uint32_t hu = (uint32_t)__bfloat16_as_ushort(hb);
            uint32_t lu = (uint32_t)__bfloat16_as_ushort(lb);
            if (k < 2) { h01 |= hu << (16 * k); l01 |= lu << (16 * k); }
            else       { h23 |= hu << (16 * (k - 2)); l23 |= lu << (16 * (k - 2)); }
        }
        size_t idx = (size_t)(b * T_ + q0 + ty * 4 + i) * 1024 + h * 64 + tx * 4;
        *(uint2*)(g_ah + idx) = make_uint2(h01, h23);
        *(uint2*)(g_al + idx) = make_uint2(l01, l23);
    }
}

static const int ATTN_SMEM = (3 * 64 * PADA + 64 * 64) * 4;

// ---------------------------------------------------------------------------
extern "C" void kernel_launch(void* const* d_in, const int* in_sizes, int n_in,
                              void* d_out, int out_size)
{
    const float* x    = (const float*)d_in[0];
    const float* Wqkv = (const float*)d_in[1];
    const float* bqkv = (const float*)d_in[2];
    const float* Wout = (const float*)d_in[3];
    const float* bout = (const float*)d_in[4];
    float* out = (float*)d_out;

    float* qkv_p; __nv_bfloat16 *ah_p, *al_p, *wqh_p, *wql_p, *woh_p, *wol_p;
    cudaGetSymbolAddress((void**)&qkv_p, g_qkv);
    cudaGetSymbolAddress((void**)&ah_p,  g_ah);
    cudaGetSymbolAddress((void**)&al_p,  g_al);
    cudaGetSymbolAddress((void**)&wqh_p, g_wqh);
    cudaGetSymbolAddress((void**)&wql_p, g_wql);
    cudaGetSymbolAddress((void**)&woh_p, g_woh);
    cudaGetSymbolAddress((void**)&wol_p, g_wol);

    cudaFuncSetAttribute(gemm_mma, cudaFuncAttributeMaxDynamicSharedMemorySize, GEMM_SMEM);
    cudaFuncSetAttribute(attn_kernel, cudaFuncAttributeMaxDynamicSharedMemorySize, ATTN_SMEM);

    const int M = B_ * T_;   // 8192

    // prep: split x; transpose+split both weights
    split_kernel<<<(M * C_ / 4 + 255) / 256, 256>>>(x, ah_p, al_p, M * C_ / 4);
    transpose_split<<<dim3(3 * C_ / 32, C_ / 32), dim3(32, 8)>>>(Wqkv, wqh_p, wql_p, C_, 3 * C_);
    transpose_split<<<dim3(C_ / 32, C_ / 32), dim3(32, 8)>>>(Wout, woh_p, wol_p, C_, C_);

    // 1) QKV projection on tensor cores (mma.sync)
    gemm_mma<<<dim3(3 * C_ / 128, M / 128), 256, GEMM_SMEM>>>(
        ah_p, al_p, wqh_p, wql_p, bqkv, qkv_p, M, 3 * C_, C_);

    // 2) RoPE
    rope_kernel<<<(M * 1024) / 256, 256>>>();

    // 3) causal flash attention (writes split output into g_ah/g_al)
    dim3 ga(T_ / 64, H_, B_);
    attn_kernel<<<ga, 256, ATTN_SMEM>>>();

    // 4) output projection on tensor cores (mma.sync)
    gemm_mma<<<dim3(C_ / 128, M / 128), 256, GEMM_SMEM>>>(
        ah_p, al_p, woh_p, wol_p, bout, out, M, C_, C_);
}

// round 11
// speedup vs baseline: 3.2088x; 1.6645x over previous
#include <cuda_runtime.h>
#include <cuda_bf16.h>
#include <cuda_fp16.h>
#include <cstdint>

#define B_  4
#define T_  2048
#define C_  1024
#define H_  16

// ---------------- device scratch (no allocs allowed) ----------------
__device__ float g_qkv[(size_t)B_ * T_ * 3 * C_];            // [8192, 3072] fp32
__device__ __nv_bfloat16 g_ah[(size_t)B_ * T_ * C_];         // A hi split [8192,1024]
__device__ __nv_bfloat16 g_al[(size_t)B_ * T_ * C_];         // A lo split
__device__ __nv_bfloat16 g_wqh[(size_t)3 * C_ * C_];         // W_qkv^T hi [3072,1024]
__device__ __nv_bfloat16 g_wql[(size_t)3 * C_ * C_];
__device__ __nv_bfloat16 g_woh[(size_t)C_ * C_];             // W_out^T hi [1024,1024]
__device__ __nv_bfloat16 g_wol[(size_t)C_ * C_];

__device__ __forceinline__ uint32_t smem_u32(const void* p) {
    uint32_t a;
    asm("{ .reg .u64 t; cvta.to.shared.u64 t, %1; cvt.u32.u64 %0, t; }" : "=r"(a) : "l"(p));
    return a;
}

#define CP16(dst, src) \
    asm volatile("cp.async.cg.shared.global [%0], [%1], 16;" :: "r"(dst), "l"(src))
#define CP_COMMIT() asm volatile("cp.async.commit_group;")
#define CP_WAIT1()  asm volatile("cp.async.wait_group 1;")
#define CP_WAIT0()  asm volatile("cp.async.wait_group 0;")

#define LDSM_X4(r0, r1, r2, r3, a) \
    asm volatile("ldmatrix.sync.aligned.m8n8.x4.shared.b16 {%0,%1,%2,%3}, [%4];" \
        : "=r"(r0), "=r"(r1), "=r"(r2), "=r"(r3) : "r"(a))

#define MMA_BF16(d, a, bv0, bv1) \
    asm volatile("mma.sync.aligned.m16n8k16.row.col.f32.bf16.bf16.f32 " \
        "{%0,%1,%2,%3}, {%4,%5,%6,%7}, {%8,%9}, {%0,%1,%2,%3};" \
        : "+f"((d)[0]), "+f"((d)[1]), "+f"((d)[2]), "+f"((d)[3]) \
        : "r"((a)[0]), "r"((a)[1]), "r"((a)[2]), "r"((a)[3]), "r"(bv0), "r"(bv1))

#define MMA_F16(d, a, bv0, bv1) \
    asm volatile("mma.sync.aligned.m16n8k16.row.col.f32.f16.f16.f32 " \
        "{%0,%1,%2,%3}, {%4,%5,%6,%7}, {%8,%9}, {%0,%1,%2,%3};" \
        : "+f"((d)[0]), "+f"((d)[1]), "+f"((d)[2]), "+f"((d)[3]) \
        : "r"((a)[0]), "r"((a)[1]), "r"((a)[2]), "r"((a)[3]), "r"(bv0), "r"(bv1))

__device__ __forceinline__ uint32_t packh2(float a, float b) {
    __half2 h = __floats2half2_rn(a, b);     // x = a (low), y = b (high)
    return *(uint32_t*)&h;
}

// ---------------- split / transpose prep ----------------
__global__ __launch_bounds__(256)
void split_kernel(const float* __restrict__ src, __nv_bfloat16* __restrict__ Dh,
                  __nv_bfloat16* __restrict__ Dl, int n4)
{
    int i = blockIdx.x * 256 + threadIdx.x;
    if (i >= n4) return;
    float4 v = *(const float4*)(src + (size_t)i * 4);
    float vs[4] = {v.x, v.y, v.z, v.w};
    uint32_t h01 = 0, h23 = 0, l01 = 0, l23 = 0;
#pragma unroll
    for (int k = 0; k < 4; k++) {
        __nv_bfloat16 hb = __float2bfloat16(vs[k]);
        __nv_bfloat16 lb = __float2bfloat16(vs[k] - __bfloat162float(hb));
        uint32_t hu = (uint32_t)__bfloat16_as_ushort(hb);
        uint32_t lu = (uint32_t)__bfloat16_as_ushort(lb);
        if (k < 2) { h01 |= hu << (16 * k); l01 |= lu << (16 * k); }
        else       { h23 |= hu << (16 * (k - 2)); l23 |= lu << (16 * (k - 2)); }
    }
    *(uint2*)(Dh + (size_t)i * 4) = make_uint2(h01, h23);
    *(uint2*)(Dl + (size_t)i * 4) = make_uint2(l01, l23);
}

__global__ __launch_bounds__(256)
void transpose_split(const float* __restrict__ W, __nv_bfloat16* __restrict__ Th,
                     __nv_bfloat16* __restrict__ Tl, int K, int N)
{   // W [K,N] row-major -> Th/Tl [N,K] row-major (bf16 hi/lo)
    __shared__ float t[32][33];
    int tx = threadIdx.x, ty = threadIdx.y;       // block (32, 8)
    int n = blockIdx.x * 32 + tx;
    int k = blockIdx.y * 32 + ty;
#pragma unroll
    for (int j = 0; j < 32; j += 8)
        t[ty + j][tx] = W[(size_t)(k + j) * N + n];
    __syncthreads();
    int k2 = blockIdx.y * 32 + tx;
    int n2 = blockIdx.x * 32 + ty;
#pragma unroll
    for (int j = 0; j < 32; j += 8) {
        float v = t[tx][ty + j];
        __nv_bfloat16 hb = __float2bfloat16(v);
        __nv_bfloat16 lb = __float2bfloat16(v - __bfloat162float(hb));
        Th[(size_t)(n2 + j) * K + k2] = hb;
        Tl[(size_t)(n2 + j) * K + k2] = lb;
    }
}

// ---------------- HMMA (mma.sync) GEMM: C = A @ B^T + bias ----------------
#define BKc   32
#define LDAB  40
#define ROWB  (LDAB * 2)               // 80 bytes
#define STG_BYTES (128 * ROWB)
#define ARR_BYTES (2 * STG_BYTES)
#define SM_AH 0
#define SM_AL (1 * ARR_BYTES)
#define SM_BH (2 * ARR_BYTES)
#define SM_BL (3 * ARR_BYTES)
#define GEMM_SMEM (4 * ARR_BYTES)      // 81920

__global__ __launch_bounds__(256)
void gemm_mma(const __nv_bfloat16* __restrict__ Ah, const __nv_bfloat16* __restrict__ Al,
              const __nv_bfloat16* __restrict__ Bh, const __nv_bfloat16* __restrict__ Bl,
              const float* __restrict__ bias, float* __restrict__ Cm,
              int M, int N, int K)
{
    extern __shared__ char sm[];
    const uint32_t sbase = smem_u32(sm);
    const int tid = threadIdx.x;
    const int wid = tid >> 5;
    const int lane = tid & 31;
    const int m0 = blockIdx.y * 128;
    const int n0 = blockIdx.x * 128;
    const int wm = (wid >> 1) * 32;
    const int wn = (wid & 1) * 64;

    float acc[2][8][4];
#pragma unroll
    for (int i = 0; i < 2; i++)
#pragma unroll
        for (int j = 0; j < 8; j++)
#pragma unroll
            for (int q = 0; q < 4; q++) acc[i][j][q] = 0.f;

    const int r_ld = tid >> 2;
    const int g_ld = tid & 3;

#define LOAD_STAGE(stg, kt)                                                     \
    do {                                                                        \
        uint32_t so = (uint32_t)(stg) * STG_BYTES;                              \
        _Pragma("unroll")                                                       \
        for (int it = 0; it < 2; it++) {                                        \
            int r = r_ld + it * 64;                                             \
            uint32_t d = so + (uint32_t)r * ROWB + g_ld * 16;                   \
            size_t ga = (size_t)(m0 + r) * K + (kt) + g_ld * 8;                 \
            size_t gb = (size_t)(n0 + r) * K + (kt) + g_ld * 8;                 \
            CP16(sbase + SM_AH + d, Ah + ga);                                   \
            CP16(sbase + SM_AL + d, Al + ga);                                   \
            CP16(sbase + SM_BH + d, Bh + gb);                                   \
            CP16(sbase + SM_BL + d, Bl + gb);                                   \
        }                                                                       \
    } while (0)

    const uint32_t a_row = wm + (lane & 15);
    const uint32_t a_col = (lane >> 4) * 8;
    const uint32_t b_row = wn + ((lane >> 4) << 3) + (lane & 7);
    const uint32_t b_col = ((lane >> 3) & 1) * 8;

    const int nchunks = K / BKc;

    LOAD_STAGE(0, 0);
    CP_COMMIT();

    for (int c = 0; c < nchunks; c++) {
        if (c + 1 < nchunks) {
            LOAD_STAGE((c + 1) & 1, (c + 1) * BKc);
            CP_COMMIT();
            CP_WAIT1();
        } else {
            CP_WAIT0();
        }
        __syncthreads();

        const uint32_t so = (uint32_t)(c & 1) * STG_BYTES;
#pragma unroll
        for (int ks = 0; ks < 2; ks++) {
            const uint32_t kc = (ks * 16 + a_col) * 2;
            const uint32_t kb = (ks * 16 + b_col) * 2;
            uint32_t ah[2][4], al[2][4], bh[4][4], bl[4][4];
#pragma unroll
            for (int mt = 0; mt < 2; mt++) {
                uint32_t ra = so + (a_row + mt * 16) * ROWB + kc;
                LDSM_X4(ah[mt][0], ah[mt][1], ah[mt][2], ah[mt][3], sbase + SM_AH + ra);
                LDSM_X4(al[mt][0], al[mt][1], al[mt][2], al[mt][3], sbase + SM_AL + ra);
            }
#pragma unroll
            for (int ng = 0; ng < 4; ng++) {
                uint32_t rb = so + (b_row + ng * 16) * ROWB + kb;
                LDSM_X4(bh[ng][0], bh[ng][1], bh[ng][2], bh[ng][3], sbase + SM_BH + rb);
                LDSM_X4(bl[ng][0], bl[ng][1], bl[ng][2], bl[ng][3], sbase + SM_BL + rb);
            }
#pragma unroll
            for (int mt = 0; mt < 2; mt++)
#pragma unroll
                for (int nt = 0; nt < 8; nt++) {
                    const int ng = nt >> 1, p = (nt & 1) * 2;
                    MMA_BF16(acc[mt][nt], ah[mt], bh[ng][p], bh[ng][p + 1]);
                    MMA_BF16(acc[mt][nt], ah[mt], bl[ng][p], bl[ng][p + 1]);
                    MMA_BF16(acc[mt][nt], al[mt], bh[ng][p], bh[ng][p + 1]);
                }
        }
        __syncthreads();
    }

    const int er = lane >> 2;
    const int ec = (lane & 3) * 2;
#pragma unroll
    for (int mt = 0; mt < 2; mt++) {
        int row = m0 + wm + mt * 16 + er;
#pragma unroll
        for (int nt = 0; nt < 8; nt++) {
            int col = n0 + wn + nt * 8 + ec;
            float b0 = bias[col], b1 = bias[col + 1];
            float2 v0 = make_float2(acc[mt][nt][0] + b0, acc[mt][nt][1] + b1);
            float2 v1 = make_float2(acc[mt][nt][2] + b0, acc[mt][nt][3] + b1);
            *(float2*)(Cm + (size_t)row * N + col) = v0;
            *(float2*)(Cm + (size_t)(row + 8) * N + col) = v1;
        }
    }
#undef LOAD_STAGE
}

// ---------------- RoPE (in place on Q,K of g_qkv) ----------------
__global__ __launch_bounds__(256)
void rope_kernel()
{
    int idx = blockIdx.x * 256 + threadIdx.x;
    int p   = idx & 1023;
    int row = idx >> 10;
    int t   = row & (T_ - 1);
    int slot = p >> 5;
    int j    = p & 31;
    int c    = slot * 64 + j;

    float invf = expf(-0.28782313662425574f * (float)j);
    float angle = (float)t * invf;
    float sv, cv;
    sincosf(angle, &sv, &cv);

    float* rowp = g_qkv + (size_t)row * 3072 + c;
    float x1 = rowp[0];
    float x2 = rowp[32];
    rowp[0]  = x1 * cv - x2 * sv;
    rowp[32] = x2 * cv + x1 * sv;
}

// ---------------- Flash attention (causal) on mma.sync, fp16 ----------------
// CTA: 64 queries x 1 head, 4 warps (16 q-rows each). K tiles of 64.
// Q A-frags preloaded (scale folded). K in smem [key][d] (B-frag ready).
// V transposed in smem [dv][key] (B-frag ready for PV). P stays in registers.
#define LDH 72   // halves per smem row (144B stride: conflict-free ldmatrix)

__global__ __launch_bounds__(128)
void attn_mma()
{
    __shared__ __half Qs[64][LDH];
    __shared__ __half Ks[64][LDH];
    __shared__ __half Vt[64][LDH];

    const int b  = blockIdx.z;
    const int h  = blockIdx.y;
    const int q0 = blockIdx.x * 64;
    const int tid = threadIdx.x;
    const int wid = tid >> 5;
    const int lane = tid & 31;

    // load Q tile (scale 1/8 folded), fp32 -> fp16
    {
        int r = tid >> 1, c0 = (tid & 1) * 32;
        const float* src = g_qkv + (size_t)(b * T_ + q0 + r) * 3072 + h * 64 + c0;
#pragma unroll
        for (int i = 0; i < 8; i++) {
            float4 v = *(const float4*)(src + i * 4);
            *(__half2*)&Qs[r][c0 + i * 4]     = __floats2half2_rn(v.x * 0.125f, v.y * 0.125f);
            *(__half2*)&Qs[r][c0 + i * 4 + 2] = __floats2half2_rn(v.z * 0.125f, v.w * 0.125f);
        }
    }
    __syncthreads();

    // Q A-fragments (validated ldmatrix pattern from gemm_mma)
    uint32_t aq[4][4];
    {
        const uint32_t arow = wid * 16 + (lane & 15);
        const uint32_t acol = (lane >> 4) * 8;
#pragma unroll
        for (int ks = 0; ks < 4; ks++)
            LDSM_X4(aq[ks][0], aq[ks][1], aq[ks][2], aq[ks][3],
                    smem_u32(&Qs[arow][ks * 16 + acol]));
    }

    float o[8][4];
#pragma unroll
    for (int i = 0; i < 8; i++)
#pragma unroll
        for (int j = 0; j < 4; j++) o[i][j] = 0.f;
    float m0 = -1e30f, m1 = -1e30f, l0 = 0.f, l1 = 0.f;

    const uint32_t brow = ((lane >> 4) << 3) + (lane & 7);
    const uint32_t bcol = ((lane >> 3) & 1) * 8;

    const int ntiles = blockIdx.x + 1;
    for (int kt = 0; kt < ntiles; kt++) {
        const int k0 = kt * 64;
        __syncthreads();
        // load K (fp16, [key][d]) and V transposed (fp16, [dv][key])
        {
            int r = tid >> 1, c0 = (tid & 1) * 32;
            const float* ksrc = g_qkv + (size_t)(b * T_ + k0 + r) * 3072 + 1024 + h * 64 + c0;
            const float* vsrc = ksrc + 1024;
#pragma unroll
            for (int i = 0; i < 8; i++) {
                float4 v = *(const float4*)(ksrc + i * 4);
                *(__half2*)&Ks[r][c0 + i * 4]     = __floats2half2_rn(v.x, v.y);
                *(__half2*)&Ks[r][c0 + i * 4 + 2] = __floats2half2_rn(v.z, v.w);
                float4 w = *(const float4*)(vsrc + i * 4);
                Vt[c0 + i * 4 + 0][r] = __float2half_rn(w.x);
                Vt[c0 + i * 4 + 1][r] = __float2half_rn(w.y);
                Vt[c0 + i * 4 + 2][r] = __float2half_rn(w.z);
                Vt[c0 + i * 4 + 3][r] = __float2half_rn(w.w);
            }
        }
        __syncthreads();

        // S = Q K^T (8 n-tiles of 8 keys)
        float s[8][4];
#pragma unroll
        for (int i = 0; i < 8; i++)
#pragma unroll
            for (int j = 0; j < 4; j++) s[i][j] = 0.f;
#pragma unroll
        for (int ks = 0; ks < 4; ks++) {
#pragma unroll
            for (int ng = 0; ng < 4; ng++) {
                uint32_t b0, b1, b2, b3;
                LDSM_X4(b0, b1, b2, b3,
                        smem_u32(&Ks[ng * 16 + brow][ks * 16 + bcol]));
                MMA_F16(s[2 * ng],     aq[ks], b0, b1);
                MMA_F16(s[2 * ng + 1], aq[ks], b2, b3);
            }
        }

        // causal mask (diagonal tile only)
        if (kt == ntiles - 1) {
            const int qr = q0 + wid * 16 + (lane >> 2);
#pragma unroll
            for (int nt = 0; nt < 8; nt++) {
                int kn = k0 + nt * 8 + (lane & 3) * 2;
                if (kn > qr)         s[nt][0] = -1e30f;
                if (kn + 1 > qr)     s[nt][1] = -1e30f;
                if (kn > qr + 8)     s[nt][2] = -1e30f;
                if (kn + 1 > qr + 8) s[nt][3] = -1e30f;
            }
        }

        // online softmax (rows r = lane>>2 and r+8)
        float t0 = -1e30f, t1 = -1e30f;
#pragma unroll
        for (int nt = 0; nt < 8; nt++) {
            t0 = fmaxf(t0, fmaxf(s[nt][0], s[nt][1]));
            t1 = fmaxf(t1, fmaxf(s[nt][2], s[nt][3]));
        }
        t0 = fmaxf(t0, __shfl_xor_sync(0xffffffffu, t0, 1));
        t0 = fmaxf(t0, __shfl_xor_sync(0xffffffffu, t0, 2));
        t1 = fmaxf(t1, __shfl_xor_sync(0xffffffffu, t1, 1));
        t1 = fmaxf(t1, __shfl_xor_sync(0xffffffffu, t1, 2));
        float mn0 = fmaxf(m0, t0), mn1 = fmaxf(m1, t1);
        float f0 = __expf(m0 - mn0), f1 = __expf(m1 - mn1);
        m0 = mn0; m1 = mn1;
        float rs0 = 0.f, rs1 = 0.f;
#pragma unroll
        for (int nt = 0; nt < 8; nt++) {
            s[nt][0] = __expf(s[nt][0] - m0);
            s[nt][1] = __expf(s[nt][1] - m0);
            s[nt][2] = __expf(s[nt][2] - m1);
            s[nt][3] = __expf(s[nt][3] - m1);
            rs0 += s[nt][0] + s[nt][1];
            rs1 += s[nt][2] + s[nt][3];
        }
        rs0 += __shfl_xor_sync(0xffffffffu, rs0, 1);
        rs0 += __shfl_xor_sync(0xffffffffu, rs0, 2);
        rs1 += __shfl_xor_sync(0xffffffffu, rs1, 1);
        rs1 += __shfl_xor_sync(0xffffffffu, rs1, 2);
        l0 = l0 * f0 + rs0;
        l1 = l1 * f1 + rs1;
#pragma unroll
        for (int nt = 0; nt < 8; nt++) {
            o[nt][0] *= f0; o[nt][1] *= f0;
            o[nt][2] *= f1; o[nt][3] *= f1;
        }

        // pack P into A-fragments (S frag layout == A frag layout)
        uint32_t pa[4][4];
#pragma unroll
        for (int ks = 0; ks < 4; ks++) {
            pa[ks][0] = packh2(s[2 * ks][0],     s[2 * ks][1]);
            pa[ks][1] = packh2(s[2 * ks][2],     s[2 * ks][3]);
            pa[ks][2] = packh2(s[2 * ks + 1][0], s[2 * ks + 1][1]);
            pa[ks][3] = packh2(s[2 * ks + 1][2], s[2 * ks + 1][3]);
        }

        // O += P V   (B-frags from Vt[dv][key])
#pragma unroll
        for (int ng = 0; ng < 4; ng++) {
#pragma unroll
            for (int ks = 0; ks < 4; ks++) {
                uint32_t b0, b1, b2, b3;
                LDSM_X4(b0, b1, b2, b3,
                        smem_u32(&Vt[ng * 16 + brow][ks * 16 + bcol]));
                MMA_F16(o[2 * ng],     pa[ks], b0, b1);
                MMA_F16(o[2 * ng + 1], pa[ks], b2, b3);
            }
        }
    }

    // epilogue: normalize + bf16 hi/lo split into g_ah/g_al
    const float inv0 = 1.f / l0, inv1 = 1.f / l1;
    const int r0 = q0 + wid * 16 + (lane >> 2);
#pragma unroll
    for (int nt = 0; nt < 8; nt++) {
        int col = h * 64 + nt * 8 + (lane & 3) * 2;
        float v0 = o[nt][0] * inv0, v1 = o[nt][1] * inv0;
        float v2 = o[nt][2] * inv1, v3 = o[nt][3] * inv1;
        {
            __nv_bfloat16 hA = __float2bfloat16(v0), hB = __float2bfloat16(v1);
            uint32_t hi = (uint32_t)__bfloat16_as_ushort(hA)
                        | ((uint32_t)__bfloat16_as_ushort(hB) << 16);
            uint32_t lo = (uint32_t)__bfloat16_as_ushort(__float2bfloat16(v0 - __bfloat162float(hA)))
                        | ((uint32_t)__bfloat16_as_ushort(__float2bfloat16(v1 - __bfloat162float(hB))) << 16);
            size_t idx = (size_t)(b * T_ + r0) * 1024 + col;
            *(uint32_t*)(g_ah + idx) = hi;
            *(uint32_t*)(g_al + idx) = lo;
        }
        {
            __nv_bfloat16 hA = __float2bfloat16(v2), hB = __float2bfloat16(v3);
            uint32_t hi = (uint32_t)__bfloat16_as_ushort(hA)
                        | ((uint32_t)__bfloat16_as_ushort(hB) << 16);
            uint32_t lo = (uint32_t)__bfloat16_as_ushort(__float2bfloat16(v2 - __bfloat162float(hA)))
                        | ((uint32_t)__bfloat16_as_ushort(__float2bfloat16(v3 - __bfloat162float(hB))) << 16);
            size_t idx = (size_t)(b * T_ + r0 + 8) * 1024 + col;
            *(uint32_t*)(g_ah + idx) = hi;
            *(uint32_t*)(g_al + idx) = lo;
        }
    }
}

// ---------------------------------------------------------------------------
extern "C" void kernel_launch(void* const* d_in, const int* in_sizes, int n_in,
                              void* d_out, int out_size)
{
    const float* x    = (const float*)d_in[0];
    const float* Wqkv = (const float*)d_in[1];
    const float* bqkv = (const float*)d_in[2];
    const float* Wout = (const float*)d_in[3];
    const float* bout = (const float*)d_in[4];
    float* out = (float*)d_out;

    float* qkv_p; __nv_bfloat16 *ah_p, *al_p, *wqh_p, *wql_p, *woh_p, *wol_p;
    cudaGetSymbolAddress((void**)&qkv_p, g_qkv);
    cudaGetSymbolAddress((void**)&ah_p,  g_ah);
    cudaGetSymbolAddress((void**)&al_p,  g_al);
    cudaGetSymbolAddress((void**)&wqh_p, g_wqh);
    cudaGetSymbolAddress((void**)&wql_p, g_wql);
    cudaGetSymbolAddress((void**)&woh_p, g_woh);
    cudaGetSymbolAddress((void**)&wol_p, g_wol);

    cudaFuncSetAttribute(gemm_mma, cudaFuncAttributeMaxDynamicSharedMemorySize, GEMM_SMEM);

    const int M = B_ * T_;   // 8192

    // prep: split x; transpose+split both weights
    split_kernel<<<(M * C_ / 4 + 255) / 256, 256>>>(x, ah_p, al_p, M * C_ / 4);
    transpose_split<<<dim3(3 * C_ / 32, C_ / 32), dim3(32, 8)>>>(Wqkv, wqh_p, wql_p, C_, 3 * C_);
    transpose_split<<<dim3(C_ / 32, C_ / 32), dim3(32, 8)>>>(Wout, woh_p, wol_p, C_, C_);

    // 1) QKV projection (split-bf16 3-pass mma.sync)
    gemm_mma<<<dim3(3 * C_ / 128, M / 128), 256, GEMM_SMEM>>>(
        ah_p, al_p, wqh_p, wql_p, bqkv, qkv_p, M, 3 * C_, C_);

    // 2) RoPE
    rope_kernel<<<(M * 1024) / 256, 256>>>();

    // 3) causal flash attention on tensor cores (fp16 mma.sync)
    attn_mma<<<dim3(T_ / 64, H_, B_), 128>>>();

    // 4) output projection (split-bf16 3-pass mma.sync)
    gemm_mma<<<dim3(C_ / 128, M / 128), 256, GEMM_SMEM>>>(
        ah_p, al_p, woh_p, wol_p, bout, out, M, C_, C_);
}

// round 15
// speedup vs baseline: 7.6200x; 2.3747x over previous
#include <cuda_runtime.h>
#include <cuda_bf16.h>
#include <cuda_fp16.h>
#include <cstdint>

#define B_  4
#define T_  2048
#define C_  1024
#define H_  16

// ---------------- device scratch (no allocs allowed) ----------------
__device__ float  g_qkv[(size_t)B_ * T_ * 3 * C_];   // QKV fp32 [8192,3072]
__device__ __half g_xh [(size_t)B_ * T_ * C_];       // x fp16 [8192,1024]
__device__ __half g_wqh[(size_t)3 * C_ * C_];        // W_qkv^T fp16 [3072,1024]
__device__ __half g_woh[(size_t)C_ * C_];            // W_out^T fp16 [1024,1024]
__device__ __half g_qh [(size_t)B_ * H_ * T_ * 64];  // Q head-major fp16 (pre-scaled)
__device__ __half g_kh [(size_t)B_ * H_ * T_ * 64];  // K head-major fp16
__device__ __half g_vt [(size_t)B_ * H_ * 64 * T_];  // V transposed fp16 [bh, d, t]
__device__ __half g_oh [(size_t)B_ * T_ * C_];       // attention out fp16 [8192,1024]

__device__ __forceinline__ uint32_t smem_u32(const void* p) {
    uint32_t a;
    asm("{ .reg .u64 t; cvta.to.shared.u64 t, %1; cvt.u32.u64 %0, t; }" : "=r"(a) : "l"(p));
    return a;
}

#define CP16(dst, src) \
    asm volatile("cp.async.cg.shared.global [%0], [%1], 16;" :: "r"(dst), "l"(src))
#define CP_COMMIT() asm volatile("cp.async.commit_group;")
#define CP_WAIT1()  asm volatile("cp.async.wait_group 1;")
#define CP_WAIT0()  asm volatile("cp.async.wait_group 0;")

#define LDSM_X4(r0, r1, r2, r3, a) \
    asm volatile("ldmatrix.sync.aligned.m8n8.x4.shared.b16 {%0,%1,%2,%3}, [%4];" \
        : "=r"(r0), "=r"(r1), "=r"(r2), "=r"(r3) : "r"(a))

#define MMA_F16(d, a, bv0, bv1) \
    asm volatile("mma.sync.aligned.m16n8k16.row.col.f32.f16.f16.f32 " \
        "{%0,%1,%2,%3}, {%4,%5,%6,%7}, {%8,%9}, {%0,%1,%2,%3};" \
        : "+f"((d)[0]), "+f"((d)[1]), "+f"((d)[2]), "+f"((d)[3]) \
        : "r"((a)[0]), "r"((a)[1]), "r"((a)[2]), "r"((a)[3]), "r"(bv0), "r"(bv1))

__device__ __forceinline__ uint32_t packh2(float a, float b) {
    __half2 h = __floats2half2_rn(a, b);
    return *(uint32_t*)&h;
}

// ---------------- prep: fp32 -> fp16 ----------------
__global__ __launch_bounds__(256)
void cvt16(const float* __restrict__ src, __half* __restrict__ dst, int n4)
{
    int i = blockIdx.x * 256 + threadIdx.x;
    if (i >= n4) return;
    float4 v = *(const float4*)(src + (size_t)i * 4);
    uint2 o;
    o.x = packh2(v.x, v.y);
    o.y = packh2(v.z, v.w);
    *(uint2*)(dst + (size_t)i * 4) = o;
}

__global__ __launch_bounds__(256)
void transpose_cvt(const float* __restrict__ W, __half* __restrict__ Tt, int K, int N)
{   // W [K,N] row-major -> Tt [N,K] row-major fp16
    __shared__ float t[32][33];
    int tx = threadIdx.x, ty = threadIdx.y;       // block (32, 8)
    int n = blockIdx.x * 32 + tx;
    int k = blockIdx.y * 32 + ty;
#pragma unroll
    for (int j = 0; j < 32; j += 8)
        t[ty + j][tx] = W[(size_t)(k + j) * N + n];
    __syncthreads();
    int k2 = blockIdx.y * 32 + tx;
    int n2 = blockIdx.x * 32 + ty;
#pragma unroll
    for (int j = 0; j < 32; j += 8)
        Tt[(size_t)(n2 + j) * K + k2] = __float2half_rn(t[tx][ty + j]);
}

// ---------------- fp16 single-pass HMMA GEMM: C = A @ B^T + bias ----------------
#define BKc   32
#define ROWB  80                       // 40 halves padded row
#define STG_BYTES (128 * ROWB)         // 10240
#define ARR_BYTES (2 * STG_BYTES)
#define SM_A 0
#define SM_B ARR_BYTES
#define GEMM_SMEM (2 * ARR_BYTES)      // 40960

__global__ __launch_bounds__(256)
void gemm16(const __half* __restrict__ A, const __half* __restrict__ Bm,
            const float* __restrict__ bias, float* __restrict__ Cm,
            int M, int N, int K)
{
    extern __shared__ char sm[];
    const uint32_t sbase = smem_u32(sm);
    const int tid = threadIdx.x;
    const int wid = tid >> 5;
    const int lane = tid & 31;
    const int m0 = blockIdx.y * 128;
    const int n0 = blockIdx.x * 128;
    const int wm = (wid >> 1) * 32;
    const int wn = (wid & 1) * 64;

    float acc[2][8][4];
#pragma unroll
    for (int i = 0; i < 2; i++)
#pragma unroll
        for (int j = 0; j < 8; j++)
#pragma unroll
            for (int q = 0; q < 4; q++) acc[i][j][q] = 0.f;

    const int r_ld = tid >> 2;
    const int g_ld = tid & 3;

#define LOAD_STAGE(stg, kt)                                                     \
    do {                                                                        \
        uint32_t so = (uint32_t)(stg) * STG_BYTES;                              \
        _Pragma("unroll")                                                       \
        for (int it = 0; it < 2; it++) {                                        \
            int r = r_ld + it * 64;                                             \
            uint32_t d = so + (uint32_t)r * ROWB + g_ld * 16;                   \
            CP16(sbase + SM_A + d, A + (size_t)(m0 + r) * K + (kt) + g_ld * 8); \
            CP16(sbase + SM_B + d, Bm + (size_t)(n0 + r) * K + (kt) + g_ld * 8);\
        }                                                                       \
    } while (0)

    const uint32_t a_row = wm + (lane & 15);
    const uint32_t a_col = (lane >> 4) * 8;
    const uint32_t b_row = wn + ((lane >> 4) << 3) + (lane & 7);
    const uint32_t b_col = ((lane >> 3) & 1) * 8;

    const int nchunks = K / BKc;

    LOAD_STAGE(0, 0);
    CP_COMMIT();

    for (int c = 0; c < nchunks; c++) {
        if (c + 1 < nchunks) {
            LOAD_STAGE((c + 1) & 1, (c + 1) * BKc);
            CP_COMMIT();
            CP_WAIT1();
        } else {
            CP_WAIT0();
        }
        __syncthreads();

        const uint32_t so = (uint32_t)(c & 1) * STG_BYTES;
#pragma unroll
        for (int ks = 0; ks < 2; ks++) {
            const uint32_t kc = (ks * 16 + a_col) * 2;
            const uint32_t kb = (ks * 16 + b_col) * 2;
            uint32_t af[2][4], bf[4][4];
#pragma unroll
            for (int mt = 0; mt < 2; mt++)
                LDSM_X4(af[mt][0], af[mt][1], af[mt][2], af[mt][3],
                        sbase + SM_A + so + (a_row + mt * 16) * ROWB + kc);
#pragma unroll
            for (int ng = 0; ng < 4; ng++)
                LDSM_X4(bf[ng][0], bf[ng][1], bf[ng][2], bf[ng][3],
                        sbase + SM_B + so + (b_row + ng * 16) * ROWB + kb);
#pragma unroll
            for (int mt = 0; mt < 2; mt++)
#pragma unroll
                for (int nt = 0; nt < 8; nt++) {
                    const int ng = nt >> 1, p = (nt & 1) * 2;
                    MMA_F16(acc[mt][nt], af[mt], bf[ng][p], bf[ng][p + 1]);
                }
        }
        __syncthreads();
    }

    const int er = lane >> 2;
    const int ec = (lane & 3) * 2;
#pragma unroll
    for (int mt = 0; mt < 2; mt++) {
        int row = m0 + wm + mt * 16 + er;
#pragma unroll
        for (int nt = 0; nt < 8; nt++) {
            int col = n0 + wn + nt * 8 + ec;
            float b0 = bias[col], b1 = bias[col + 1];
            float2 v0 = make_float2(acc[mt][nt][0] + b0, acc[mt][nt][1] + b1);
            float2 v1 = make_float2(acc[mt][nt][2] + b0, acc[mt][nt][3] + b1);
            *(float2*)(Cm + (size_t)row * N + col) = v0;
            *(float2*)(Cm + (size_t)(row + 8) * N + col) = v1;
        }
    }
#undef LOAD_STAGE
}

// ---------------- RoPE: fp32 QKV -> fp16 head-major Qh (scaled), Kh ----------------
__global__ __launch_bounds__(256)
void rope_kernel()
{
    int idx = blockIdx.x * 256 + threadIdx.x;
    int p   = idx & 1023;
    int row = idx >> 10;
    int b   = row >> 11;
    int t   = row & (T_ - 1);
    int slot = p >> 5;
    int j    = p & 31;

    float invf = expf(-0.28782313662425574f * (float)j);
    float angle = (float)t * invf;
    float sv, cv;
    sincosf(angle, &sv, &cv);

    const float* rp = g_qkv + (size_t)row * 3072 + slot * 64 + j;
    float x1 = rp[0];
    float x2 = rp[32];
    float y1 = x1 * cv - x2 * sv;
    float y2 = x2 * cv + x1 * sv;

    if (slot < 16) {
        __half* dst = g_qh + ((size_t)(b * H_ + slot) * T_ + t) * 64;
        dst[j]      = __float2half_rn(y1 * 0.125f);
        dst[j + 32] = __float2half_rn(y2 * 0.125f);
    } else {
        __half* dst = g_kh + ((size_t)(b * H_ + slot - 16) * T_ + t) * 64;
        dst[j]      = __float2half_rn(y1);
        dst[j + 32] = __float2half_rn(y2);
    }
}

// ---------------- V: fp32 token-major -> fp16 transposed [bh, d, t] ----------------
__global__ __launch_bounds__(256)
void v_transpose()
{
    __shared__ float t[32][33];
    int tx = threadIdx.x, ty = threadIdx.y;       // block (32, 8)
    int bh = blockIdx.z;
    int b  = bh >> 4, h = bh & 15;
    int t0 = blockIdx.x * 32;
    int d0 = blockIdx.y * 32;
#pragma unroll
    for (int j = 0; j < 32; j += 8)
        t[ty + j][tx] = g_qkv[(size_t)(b * T_ + t0 + ty + j) * 3072 + 2048 + h * 64 + d0 + tx];
    __syncthreads();
#pragma unroll
    for (int j = 0; j < 32; j += 8)
        g_vt[((size_t)bh * 64 + d0 + ty + j) * T_ + t0 + tx] = __float2half_rn(t[tx][ty + j]);
}

// ---------------- Flash attention (causal) on mma.sync, fp16, pipelined ----------------
#define LDH 72   // halves per smem row (144B stride)

__global__ __launch_bounds__(128)
void attn_mma()
{
    __shared__ __half Qs[64][LDH];
    __shared__ __half Ks[2][64][LDH];
    __shared__ __half Vs[2][64][LDH];

    const int b  = blockIdx.z;
    const int h  = blockIdx.y;
    const int q0 = blockIdx.x * 64;
    const int tid = threadIdx.x;
    const int wid = tid >> 5;
    const int lane = tid & 31;

    const uint32_t qs_u = smem_u32(&Qs[0][0]);
    const uint32_t ks_u = smem_u32(&Ks[0][0][0]);
    const uint32_t vs_u = smem_u32(&Vs[0][0][0]);
    const uint32_t stg = 64 * LDH * 2;            // bytes per stage buffer

    const __half* qbase = g_qh + ((size_t)(b * H_ + h) * T_ + q0) * 64;
    const __half* kbase = g_kh + (size_t)(b * H_ + h) * T_ * 64;
    const __half* vbase = g_vt + (size_t)(b * H_ + h) * 64 * T_;

    // Q tile: 64 rows x 64 halves = 512 16B chunks, 4 per thread
#pragma unroll
    for (int i = 0; i < 4; i++) {
        int c = tid + i * 128;
        CP16(qs_u + (c >> 3) * 144 + (c & 7) * 16, qbase + c * 8);
    }

#define LOAD_TILE(st, kt)                                                       \
    do {                                                                        \
        const __half* kb = kbase + (size_t)(kt) * 64 * 64;                      \
        _Pragma("unroll")                                                       \
        for (int i = 0; i < 4; i++) {                                           \
            int c = tid + i * 128;                                              \
            CP16(ks_u + (st) * stg + (c >> 3) * 144 + (c & 7) * 16, kb + c * 8);\
        }                                                                       \
        const __half* vb = vbase + (size_t)(kt) * 64;                           \
        _Pragma("unroll")                                                       \
        for (int i = 0; i < 4; i++) {                                           \
            int c = tid + i * 128;                                              \
            CP16(vs_u + (st) * stg + (c >> 3) * 144 + (c & 7) * 16,             \
                 vb + (size_t)(c >> 3) * T_ + (c & 7) * 8);                     \
        }                                                                       \
    } while (0)

    LOAD_TILE(0, 0);
    CP_COMMIT();
    CP_WAIT0();
    __syncthreads();

    // Q A-fragments
    uint32_t aq[4][4];
    {
        const uint32_t arow = wid * 16 + (lane & 15);
        const uint32_t acol = (lane >> 4) * 8;
#pragma unroll
        for (int ks = 0; ks < 4; ks++)
            LDSM_X4(aq[ks][0], aq[ks][1], aq[ks][2], aq[ks][3],
                    qs_u + arow * 144 + (ks * 16 + acol) * 2);
    }

    float o[8][4];
#pragma unroll
    for (int i = 0; i < 8; i++)
#pragma unroll
        for (int j = 0; j < 4; j++) o[i][j] = 0.f;
    float m0 = -1e30f, m1 = -1e30f, l0 = 0.f, l1 = 0.f;

    const uint32_t brow = ((lane >> 4) << 3) + (lane & 7);
    const uint32_t bcol = ((lane >> 3) & 1) * 8;

    const int ntiles = blockIdx.x + 1;
    for (int kt = 0; kt < ntiles; kt++) {
        if (kt + 1 < ntiles) {
            LOAD_TILE((kt + 1) & 1, kt + 1);
            CP_COMMIT();
            CP_WAIT1();
        } else {
            CP_WAIT0();
        }
        __syncthreads();

        const uint32_t so = (uint32_t)(kt & 1) * stg;
        const int k0 = kt * 64;

        // S = Q K^T
        float s[8][4];
#pragma unroll
        for (int i = 0; i < 8; i++)
#pragma unroll
            for (int j = 0; j < 4; j++) s[i][j] = 0.f;
#pragma unroll
        for (int ks = 0; ks < 4; ks++) {
#pragma unroll
            for (int ng = 0; ng < 4; ng++) {
                uint32_t b0, b1, b2, b3;
                LDSM_X4(b0, b1, b2, b3,
                        ks_u + so + (ng * 16 + brow) * 144 + (ks * 16 + bcol) * 2);
                MMA_F16(s[2 * ng],     aq[ks], b0, b1);
                MMA_F16(s[2 * ng + 1], aq[ks], b2, b3);
            }
        }

        // causal mask (diagonal tile only)
        if (kt == ntiles - 1) {
            const int qr = q0 + wid * 16 + (lane >> 2);
#pragma unroll
            for (int nt = 0; nt < 8; nt++) {
                int kn = k0 + nt * 8 + (lane & 3) * 2;
                if (kn > qr)         s[nt][0] = -1e30f;
                if (kn + 1 > qr)     s[nt][1] = -1e30f;
                if (kn > qr + 8)     s[nt][2] = -1e30f;
                if (kn + 1 > qr + 8) s[nt][3] = -1e30f;
            }
        }

        // online softmax (rows lane>>2 and +8)
        float t0 = -1e30f, t1 = -1e30f;
#pragma unroll
        for (int nt = 0; nt < 8; nt++) {
            t0 = fmaxf(t0, fmaxf(s[nt][0], s[nt][1]));
            t1 = fmaxf(t1, fmaxf(s[nt][2], s[nt][3]));
        }
        t0 = fmaxf(t0, __shfl_xor_sync(0xffffffffu, t0, 1));
        t0 = fmaxf(t0, __shfl_xor_sync(0xffffffffu, t0, 2));
        t1 = fmaxf(t1, __shfl_xor_sync(0xffffffffu, t1, 1));
        t1 = fmaxf(t1, __shfl_xor_sync(0xffffffffu, t1, 2));
        float mn0 = fmaxf(m0, t0), mn1 = fmaxf(m1, t1);
        float f0 = __expf(m0 - mn0), f1 = __expf(m1 - mn1);
        m0 = mn0; m1 = mn1;
        float rs0 = 0.f, rs1 = 0.f;
#pragma unroll
        for (int nt = 0; nt < 8; nt++) {
            s[nt][0] = __expf(s[nt][0] - m0);
            s[nt][1] = __expf(s[nt][1] - m0);
            s[nt][2] = __expf(s[nt][2] - m1);
            s[nt][3] = __expf(s[nt][3] - m1);
            rs0 += s[nt][0] + s[nt][1];
            rs1 += s[nt][2] + s[nt][3];
        }
        rs0 += __shfl_xor_sync(0xffffffffu, rs0, 1);
        rs0 += __shfl_xor_sync(0xffffffffu, rs0, 2);
        rs1 += __shfl_xor_sync(0xffffffffu, rs1, 1);
        rs1 += __shfl_xor_sync(0xffffffffu, rs1, 2);
        l0 = l0 * f0 + rs0;
        l1 = l1 * f1 + rs1;
#pragma unroll
        for (int nt = 0; nt < 8; nt++) {
            o[nt][0] *= f0; o[nt][1] *= f0;
            o[nt][2] *= f1; o[nt][3] *= f1;
        }

        // pack P into A-fragments
        uint32_t pa[4][4];
#pragma unroll
        for (int ks = 0; ks < 4; ks++) {
            pa[ks][0] = packh2(s[2 * ks][0],     s[2 * ks][1]);
            pa[ks][1] = packh2(s[2 * ks][2],     s[2 * ks][3]);
            pa[ks][2] = packh2(s[2 * ks + 1][0], s[2 * ks + 1][1]);
            pa[ks][3] = packh2(s[2 * ks + 1][2], s[2 * ks + 1][3]);
        }

        // O += P V
#pragma unroll
        for (int ng = 0; ng < 4; ng++) {
#pragma unroll
            for (int ks = 0; ks < 4; ks++) {
                uint32_t b0, b1, b2, b3;
                LDSM_X4(b0, b1, b2, b3,
                        vs_u + so + (ng * 16 + brow) * 144 + (ks * 16 + bcol) * 2);
                MMA_F16(o[2 * ng],     pa[ks], b0, b1);
                MMA_F16(o[2 * ng + 1], pa[ks], b2, b3);
            }
        }
        __syncthreads();
    }

    // epilogue: normalize, write fp16 O (token-major) for out-proj
    const float inv0 = 1.f / l0, inv1 = 1.f / l1;
    const int r0 = q0 + wid * 16 + (lane >> 2);
#pragma unroll
    for (int nt = 0; nt < 8; nt++) {
        int col = h * 64 + nt * 8 + (lane & 3) * 2;
        size_t i0 = (size_t)(b * T_ + r0) * 1024 + col;
        size_t i1 = (size_t)(b * T_ + r0 + 8) * 1024 + col;
        *(uint32_t*)(g_oh + i0) = packh2(o[nt][0] * inv0, o[nt][1] * inv0);
        *(uint32_t*)(g_oh + i1) = packh2(o[nt][2] * inv1, o[nt][3] * inv1);
    }
#undef LOAD_TILE
}

// ---------------------------------------------------------------------------
extern "C" void kernel_launch(void* const* d_in, const int* in_sizes, int n_in,
                              void* d_out, int out_size)
{
    const float* x    = (const float*)d_in[0];
    const float* Wqkv = (const float*)d_in[1];
    const float* bqkv = (const float*)d_in[2];
    const float* Wout = (const float*)d_in[3];
    const float* bout = (const float*)d_in[4];
    float* out = (float*)d_out;

    float* qkv_p; __half *xh_p, *wqh_p, *woh_p, *oh_p;
    cudaGetSymbolAddress((void**)&qkv_p, g_qkv);
    cudaGetSymbolAddress((void**)&xh_p,  g_xh);
    cudaGetSymbolAddress((void**)&wqh_p, g_wqh);
    cudaGetSymbolAddress((void**)&woh_p, g_woh);
    cudaGetSymbolAddress((void**)&oh_p,  g_oh);

    cudaFuncSetAttribute(gemm16, cudaFuncAttributeMaxDynamicSharedMemorySize, GEMM_SMEM);

    const int M = B_ * T_;   // 8192

    // prep: convert x; transpose+convert weights (fp16)
    cvt16<<<(M * C_ / 4 + 255) / 256, 256>>>(x, xh_p, M * C_ / 4);
    transpose_cvt<<<dim3(3 * C_ / 32, C_ / 32), dim3(32, 8)>>>(Wqkv, wqh_p, C_, 3 * C_);
    transpose_cvt<<<dim3(C_ / 32, C_ / 32), dim3(32, 8)>>>(Wout, woh_p, C_, C_);

    // 1) QKV projection (fp16 mma.sync, single pass)
    gemm16<<<dim3(3 * C_ / 128, M / 128), 256, GEMM_SMEM>>>(
        xh_p, wqh_p, bqkv, qkv_p, M, 3 * C_, C_);

    // 2) RoPE -> fp16 head-major Qh (scaled), Kh;  V -> fp16 transposed
    rope_kernel<<<(M * 1024) / 256, 256>>>();
    v_transpose<<<dim3(T_ / 32, 2, B_ * H_), dim3(32, 8)>>>();

    // 3) causal flash attention (fp16 mma.sync, 2-stage cp.async pipeline)
    attn_mma<<<dim3(T_ / 64, H_, B_), 128>>>();

    // 4) output projection (fp16 mma.sync, single pass)
    gemm16<<<dim3(C_ / 128, M / 128), 256, GEMM_SMEM>>>(
        oh_p, woh_p, bout, out, M, C_, C_);
}